// round 14
// baseline (speedup 1.0000x reference)
#include <cuda_runtime.h>

// SSIM loss, fused separable 11x11 Gaussian, B=16 C=3 H=512 W=512 fp32.
// v14 = v13 with the ring-prologue off-by-one FIXED (load into ra[1..10]).
//   BARRIER-FREE mainloop via shuffle-based horizontal conv.
//   160 threads = 5 warps per block; warp w covers input cols [96w,96w+128)
//   (32-col overlap -> +25% redundant vertical, the price of decoupling);
//   output ranges 112/96/96/96/112 cols, lane-masked accumulate.
//   Vertical conv: register ring of 11 packed rows, packed-weight f32x2,
//   merged-q (4 accumulator pairs). Incoming rows via cp.async.cg 2-slot
//   thread-private smem staging issued 2 rows ahead.
//   Horizontal conv: vertical sums stay in registers; the ±5-col window is
//   gathered with __shfl_up/down (intra-warp by construction); 11 FFMA-imm
//   per output. No __syncthreads, no line buffer, warps fully decoupled.
//   grid = (6 chunks, 48 planes) = 288 blocks = 148 SM x 2 CTAs, 1 wave.
//   Finalize folded into the last block (atomicInc wrap, replay-safe).

#define HH 512
#define WW 512
#define NTHREADS 160
#define NPIX 12582912.0
#define GX 6
#define GY 48
#define NBLOCKS (GX * GY)
#define FULLM 0xFFFFFFFFu

typedef unsigned long long u64;

__device__ constexpr float KW[11] = {
    0.00102839f, 0.00759876f, 0.03600077f, 0.10936069f, 0.21300554f,
    0.26601172f,
    0.21300554f, 0.10936069f, 0.03600077f, 0.00759876f, 0.00102839f};

__device__ double g_partial[NBLOCKS];
__device__ unsigned g_count = 0;

// ---- f32x2 packed helpers (sm_100+ PTX) ----
__device__ __forceinline__ u64 pk2(float lo, float hi) {
    u64 r; asm("mov.b64 %0, {%1, %2};" : "=l"(r) : "f"(lo), "f"(hi)); return r;
}
__device__ __forceinline__ void upk2(u64 v, float& lo, float& hi) {
    asm("mov.b64 {%0, %1}, %2;" : "=f"(lo), "=f"(hi) : "l"(v));
}
__device__ __forceinline__ u64 f2add(u64 a, u64 b) {
    u64 r; asm("add.rn.f32x2 %0, %1, %2;" : "=l"(r) : "l"(a), "l"(b)); return r;
}
__device__ __forceinline__ u64 f2mul(u64 a, u64 b) {
    u64 r; asm("mul.rn.f32x2 %0, %1, %2;" : "=l"(r) : "l"(a), "l"(b)); return r;
}
__device__ __forceinline__ u64 f2fma(u64 a, u64 b, u64 c) {
    u64 r; asm("fma.rn.f32x2 %0, %1, %2, %3;" : "=l"(r) : "l"(a), "l"(b), "l"(c));
    return r;
}

// ---- cp.async helpers ----
__device__ __forceinline__ void cp16(unsigned dst, const float* src) {
    asm volatile("cp.async.cg.shared.global [%0], [%1], 16;"
                 :: "r"(dst), "l"(src));
}
#define CP_COMMIT() asm volatile("cp.async.commit_group;" ::: "memory")
#define CP_WAIT1()  asm volatile("cp.async.wait_group 1;" ::: "memory")

__device__ __forceinline__ void load_row_pk(const float* __restrict__ base,
                                            int row, u64 o[2]) {
    if ((unsigned)row < (unsigned)HH) {
        ulonglong2 v =
            *reinterpret_cast<const ulonglong2*>(base + (size_t)row * WW);
        o[0] = v.x;
        o[1] = v.y;
    } else {
        o[0] = 0ull; o[1] = 0ull;
    }
}

__global__ __launch_bounds__(NTHREADS, 2)
void ssim_kernel(const float* __restrict__ sr, const float* __restrict__ hr,
                 float* __restrict__ out) {
    const int plane = blockIdx.y;
    const int bx = blockIdx.x;
    // chunks: 86,86,86,86,84,84 (sum 512)
    const int r0 = (bx < 4) ? 86 * bx : (344 + 84 * (bx - 4));
    const int nrows = (bx < 4) ? 86 : 84;
    const int tid = threadIdx.x;
    const int wid = tid >> 5;        // 0..4
    const int lane = tid & 31;
    const int gcol = 96 * wid + 4 * lane;   // this thread's 4 input cols

    // output-active predicate (ranges aligned to 4-col lanes)
    const int lo = (wid == 0) ? 0 : (96 * wid + 16);
    const int hi = (wid == 4) ? 512 : (96 * wid + 112);
    const bool active = (gcol >= lo) && (gcol < hi);

    const float* __restrict__ pa0 = sr + (size_t)plane * HH * WW + gcol;
    const float* __restrict__ pb0 = hr + (size_t)plane * HH * WW + gcol;

    // cp.async staging, thread-linear indexing (gcol overlaps across warps)
    __shared__ __align__(16) float stageA[2][NTHREADS * 4];
    __shared__ __align__(16) float stageB[2][NTHREADS * 4];
    unsigned sA[2], sB[2];
#pragma unroll
    for (int s = 0; s < 2; ++s) {
        sA[s] = (unsigned)__cvta_generic_to_shared(&stageA[s][tid * 4]);
        sB[s] = (unsigned)__cvta_generic_to_shared(&stageB[s][tid * 4]);
    }

    // Packed weight constants (symmetric kernel -> 6 uniques).
    u64 WKP[6];
#pragma unroll
    for (int k = 0; k < 6; ++k) WKP[k] = pk2(KW[k], KW[k]);

    // Register ring: after each shift, positions 0..10 hold source rows
    // (i-5)..(i+5) for output row i. Prologue fills positions 1..10 with
    // rows r0-5 .. r0+4 (the FIX: was 0..9 in v13).
    u64 ra[11][2], rb[11][2];
#pragma unroll
    for (int k = 0; k < 10; ++k) {
        load_row_pk(pa0, r0 - 5 + k, ra[k + 1]);
        load_row_pk(pb0, r0 - 5 + k, rb[k + 1]);
    }
    // Prologue staging: rows r0+5, r0+6 (< HH since r0 <= 428).
    {
        int g5 = r0 + 5, g6 = r0 + 6;
        cp16(sA[g5 & 1], pa0 + (size_t)g5 * WW);
        cp16(sB[g5 & 1], pb0 + (size_t)g5 * WW);
        CP_COMMIT();
        cp16(sA[g6 & 1], pa0 + (size_t)g6 * WW);
        cp16(sB[g6 & 1], pb0 + (size_t)g6 * WW);
        CP_COMMIT();
    }

    float acc = 0.f;

#pragma unroll 2
    for (int i = 0; i < nrows; ++i) {
        const int gr = r0 + i + 5;      // incoming ring row
        const int slot = gr & 1;

        // consume staged row gr (issued 2 rows ago)
        CP_WAIT1();
        ulonglong2 ta = *reinterpret_cast<const ulonglong2*>(&stageA[slot][tid * 4]);
        ulonglong2 tb = *reinterpret_cast<const ulonglong2*>(&stageB[slot][tid * 4]);
        if (gr >= HH) { ta.x = 0; ta.y = 0; tb.x = 0; tb.y = 0; }

        // shift ring, push incoming row
#pragma unroll
        for (int k = 0; k < 10; ++k) {
#pragma unroll
            for (int q = 0; q < 2; ++q) {
                ra[k][q] = ra[k + 1][q];
                rb[k][q] = rb[k + 1][q];
            }
        }
        ra[10][0] = ta.x; ra[10][1] = ta.y;
        rb[10][0] = tb.x; rb[10][1] = tb.y;

        // refill staging with row gr+2 (same slot parity), clamped
        {
            int rc = (gr + 2 < HH) ? (gr + 2) : (HH - 1);
            cp16(sA[slot], pa0 + (size_t)rc * WW);
            cp16(sB[slot], pb0 + (size_t)rc * WW);
            CP_COMMIT();
        }

        // ---- vertical 11-tap conv, packed, merged-q (4 acc pairs) ----
        u64 s0[2], s1[2], sq[2], sp[2];
#pragma unroll
        for (int q = 0; q < 2; ++q) {
            u64 a = ra[5][q], b = rb[5][q];
            u64 qrow = f2fma(b, b, f2mul(a, a));
            u64 ab = f2mul(a, b);
            s0[q] = f2mul(WKP[5], a);
            s1[q] = f2mul(WKP[5], b);
            sq[q] = f2mul(WKP[5], qrow);
            sp[q] = f2mul(WKP[5], ab);
        }
#pragma unroll
        for (int k = 0; k < 11; ++k) {
            if (k == 5) continue;
            const int wi = (k < 5) ? k : (10 - k);
#pragma unroll
            for (int q = 0; q < 2; ++q) {
                u64 a = ra[k][q], b = rb[k][q];
                u64 qrow = f2fma(b, b, f2mul(a, a));
                u64 ab = f2mul(a, b);
                s0[q] = f2fma(WKP[wi], a, s0[q]);
                s1[q] = f2fma(WKP[wi], b, s1[q]);
                sq[q] = f2fma(WKP[wi], qrow, sq[q]);
                sp[q] = f2fma(WKP[wi], ab, sp[q]);
            }
        }

        // ---- shuffle-based horizontal conv + map (NO barrier) ----
        float cv[4][4];
#pragma unroll
        for (int f = 0; f < 4; ++f) {
            const u64* accp = (f == 0) ? s0 : (f == 1) ? s1 : (f == 2) ? sq : sp;
            float o0, o1, o2, o3;
            upk2(accp[0], o0, o1);
            upk2(accp[1], o2, o3);
            // remote window floats via intra-warp shuffles
            float l5 = __shfl_up_sync(FULLM, o3, 2);    // c0-5
            float l4 = __shfl_up_sync(FULLM, o0, 1);    // c0-4
            float l3 = __shfl_up_sync(FULLM, o1, 1);    // c0-3
            float l2 = __shfl_up_sync(FULLM, o2, 1);    // c0-2
            float l1 = __shfl_up_sync(FULLM, o3, 1);    // c0-1
            float r1 = __shfl_down_sync(FULLM, o0, 1);  // c0+4
            float r2 = __shfl_down_sync(FULLM, o1, 1);  // c0+5
            float r3 = __shfl_down_sync(FULLM, o2, 1);  // c0+6
            float r4 = __shfl_down_sync(FULLM, o3, 1);  // c0+7
            float r5 = __shfl_down_sync(FULLM, o0, 2);  // c0+8
            // image-edge zero fixups (only warps 0 and 4; uniform branch)
            if (wid == 0) {
                if (lane == 0) { l4 = 0.f; l3 = 0.f; l2 = 0.f; l1 = 0.f; }
                if (lane <= 1) { l5 = 0.f; }
            }
            if (wid == 4) {
                if (lane == 31) { r1 = 0.f; r2 = 0.f; r3 = 0.f; r4 = 0.f; }
                if (lane >= 30) { r5 = 0.f; }
            }
            float v[14] = {l5, l4, l3, l2, l1, o0, o1, o2, o3,
                           r1, r2, r3, r4, r5};
#pragma unroll
            for (int j = 0; j < 4; ++j) {
                float s = KW[5] * v[5 + j];
#pragma unroll
                for (int k = 0; k < 11; ++k) {
                    if (k == 5) continue;
                    s += KW[k] * v[j + k];
                }
                cv[f][j] = s;
            }
        }

        // SSIM map (scalar, 4 cols), lane-masked accumulate
        if (active) {
#pragma unroll
            for (int j = 0; j < 4; ++j) {
                float m1 = cv[0][j], m2 = cv[1][j];
                float qv = cv[2][j], pv = cv[3][j];
                float m12 = m1 * m2;
                float sms = fmaf(m1, m1, m2 * m2);
                float num1 = fmaf(m12, 2.f, 1e-4f);
                float num2 = fmaf(pv - m12, 2.f, 9e-4f);
                float den1 = sms + 1e-4f;
                float den2 = (qv - sms) + 9e-4f;
                acc += __fdividef(num1 * num2, den1 * den2);
            }
        }
    }

    // block reduction -> per-block partial
#pragma unroll
    for (int o = 16; o > 0; o >>= 1)
        acc += __shfl_down_sync(FULLM, acc, o);

    __shared__ float wsum[5];
    __shared__ int is_last;
    if (lane == 0) wsum[wid] = acc;
    __syncthreads();
    if (tid == 0) {
        double s = 0.0;
#pragma unroll
        for (int w = 0; w < 5; ++w) s += (double)wsum[w];
        g_partial[blockIdx.y * GX + blockIdx.x] = s;
        __threadfence();
        unsigned old = atomicInc(&g_count, NBLOCKS - 1);  // wraps to 0
        is_last = (old == NBLOCKS - 1);
    }
    __syncthreads();

    // last block finalizes (replay-deterministic: counter wraps to 0)
    if (is_last) {
        __threadfence();
        double s = 0.0;
        for (int i2 = tid; i2 < NBLOCKS; i2 += NTHREADS)
            s += __ldcg(&g_partial[i2]);
#pragma unroll
        for (int o = 16; o > 0; o >>= 1)
            s += __shfl_down_sync(FULLM, s, o);
        __shared__ double dsm[5];
        if (lane == 0) dsm[wid] = s;
        __syncthreads();
        if (tid == 0) {
            double tot = 0.0;
#pragma unroll
            for (int w = 0; w < 5; ++w) tot += dsm[w];
            out[0] = (float)(1.0 - tot / NPIX);
        }
    }
}

extern "C" void kernel_launch(void* const* d_in, const int* in_sizes, int n_in,
                              void* d_out, int out_size) {
    const float* sr = (const float*)d_in[0];
    const float* hr = (const float*)d_in[1];
    float* out = (float*)d_out;

    dim3 grid(GX, GY);
    ssim_kernel<<<grid, NTHREADS>>>(sr, hr, out);
}

// round 15
// speedup vs baseline: 1.6258x; 1.6258x over previous
#include <cuda_runtime.h>

// SSIM loss, fused separable 11x11 Gaussian, B=16 C=3 H=512 W=512 fp32.
// v15 = v12 (shared-product streamed vertical + cp.async staging) with
//   liveness fixes: #pragma unroll 1 on the pair loop (prevents cross-pair
//   hoisting of staged reads -> no spill) and scalar SSIM map (frees the
//   packed-constant registers).
//   grid = (9 chunks, 48 planes) = 432 blocks, 128 thr, 4 cols/thread,
//   3 CTAs/SM. Ring of 10 packed rows (i-5..i+4); rows i+5, i+6 via
//   cp.async.cg 2-slot staging issued 2 rows ahead. Vertical conv streams
//   the 12 source rows once, computing (a^2+b^2),(ab) once per source row,
//   accumulating into BOTH output rows (248 packed ops/pair vs 308).
//   Horizontal: scalar FFMA-imm from quad-buffered padded smem,
//   ONE __syncthreads per 2 rows. Finalize folded into the last block.

#define HH 512
#define WW 512
#define NTHREADS 128
#define NPIX 12582912.0
#define GX 9
#define GY 48
#define NBLOCKS (GX * GY)
#define FULLM 0xFFFFFFFFu

typedef unsigned long long u64;

__device__ constexpr float KW[11] = {
    0.00102839f, 0.00759876f, 0.03600077f, 0.10936069f, 0.21300554f,
    0.26601172f,
    0.21300554f, 0.10936069f, 0.03600077f, 0.00759876f, 0.00102839f};

__device__ double g_partial[NBLOCKS];
__device__ unsigned g_count = 0;

// ---- f32x2 packed helpers (sm_100+ PTX) ----
__device__ __forceinline__ u64 pk2(float lo, float hi) {
    u64 r; asm("mov.b64 %0, {%1, %2};" : "=l"(r) : "f"(lo), "f"(hi)); return r;
}
__device__ __forceinline__ void upk2(u64 v, float& lo, float& hi) {
    asm("mov.b64 {%0, %1}, %2;" : "=f"(lo), "=f"(hi) : "l"(v));
}
__device__ __forceinline__ u64 f2add(u64 a, u64 b) {
    u64 r; asm("add.rn.f32x2 %0, %1, %2;" : "=l"(r) : "l"(a), "l"(b)); return r;
}
__device__ __forceinline__ u64 f2mul(u64 a, u64 b) {
    u64 r; asm("mul.rn.f32x2 %0, %1, %2;" : "=l"(r) : "l"(a), "l"(b)); return r;
}
__device__ __forceinline__ u64 f2fma(u64 a, u64 b, u64 c) {
    u64 r; asm("fma.rn.f32x2 %0, %1, %2, %3;" : "=l"(r) : "l"(a), "l"(b), "l"(c));
    return r;
}

// ---- cp.async helpers ----
__device__ __forceinline__ void cp16(unsigned dst, const float* src) {
    asm volatile("cp.async.cg.shared.global [%0], [%1], 16;"
                 :: "r"(dst), "l"(src));
}
#define CP_COMMIT() asm volatile("cp.async.commit_group;" ::: "memory")
#define CP_WAIT1()  asm volatile("cp.async.wait_group 1;" ::: "memory")

__device__ __forceinline__ void load_row_pk(const float* __restrict__ base,
                                            int row, int c0, u64 o[2]) {
    if ((unsigned)row < (unsigned)HH) {
        ulonglong2 v = *reinterpret_cast<const ulonglong2*>(
            base + (size_t)row * WW + c0);
        o[0] = v.x;
        o[1] = v.y;
    } else {
        o[0] = 0ull; o[1] = 0ull;
    }
}

__global__ __launch_bounds__(NTHREADS, 3)
void ssim_kernel(const float* __restrict__ sr, const float* __restrict__ hr,
                 float* __restrict__ out) {
    const int plane = blockIdx.y;
    const int bx = blockIdx.x;
    // chunks: 58,58,58,58,56,56,56,56,56 (all even; sum = 512)
    const int r0 = (bx < 4) ? 58 * bx : (232 + 56 * (bx - 4));
    const int npairs = (bx < 4) ? 29 : 28;
    const int tid = threadIdx.x;
    const int c0 = tid * 4;

    const float* __restrict__ pa0 = sr + (size_t)plane * HH * WW + c0;
    const float* __restrict__ pb0 = hr + (size_t)plane * HH * WW + c0;

    // Quad-buffered line buffer: [buf 0..3][field 0..3], data col c at word
    // c+8, halo zeros at words [0..7] and [520..527].
    __shared__ __align__(16) float vsbuf[4][4][528];
    // cp.async staging: 2 slots (by incoming-row parity) x 2 tensors.
    __shared__ __align__(16) float stageA[2][WW];
    __shared__ __align__(16) float stageB[2][WW];

    {
        for (int q = tid; q < 256; q += NTHREADS) {
            int b = q >> 6;
            int f = (q >> 4) & 3;
            int k = q & 15;
            int idx = (k < 8) ? k : (512 + k);
            vsbuf[b][f][idx] = 0.f;
        }
    }
    __syncthreads();

    unsigned sA[2], sB[2];
#pragma unroll
    for (int s = 0; s < 2; ++s) {
        sA[s] = (unsigned)__cvta_generic_to_shared(&stageA[s][c0]);
        sB[s] = (unsigned)__cvta_generic_to_shared(&stageB[s][c0]);
    }

    // Packed weight constants (symmetric kernel -> 6 uniques).
    u64 WKP[6];
#pragma unroll
    for (int k = 0; k < 6; ++k) WKP[k] = pk2(KW[k], KW[k]);

    // Register ring: positions 0..9 hold source rows (i-5) .. (i+4).
    u64 rga[10][2], rgb[10][2];
#pragma unroll
    for (int k = 0; k < 10; ++k) {
        load_row_pk(pa0 - c0, r0 - 5 + k, c0, rga[k]);
        load_row_pk(pb0 - c0, r0 - 5 + k, c0, rgb[k]);
    }

    // Prologue staging: rows r0+5, r0+6 (both < HH since r0 <= 456).
    {
        int g5 = r0 + 5, g6 = r0 + 6;
        cp16(sA[g5 & 1], pa0 + (size_t)g5 * WW);
        cp16(sB[g5 & 1], pb0 + (size_t)g5 * WW);
        CP_COMMIT();
        cp16(sA[g6 & 1], pa0 + (size_t)g6 * WW);
        cp16(sB[g6 & 1], pb0 + (size_t)g6 * WW);
        CP_COMMIT();
    }

    float acc = 0.f;

#pragma unroll 1
    for (int p = 0; p < npairs; ++p) {
        const int bufA = (p & 1) * 2;
        const int bufB = bufA + 1;
        const int i = r0 + 2 * p;

        // ---- consume staged rows i+5, i+6; refill slots with i+7, i+8 ----
        u64 st5a[2], st5b[2], st6a[2], st6b[2];
        {
            const int g5 = i + 5, g6 = i + 6;
            const int sl5 = g5 & 1, sl6 = g6 & 1;

            CP_WAIT1();  // row g5 complete
            ulonglong2 ta = *reinterpret_cast<const ulonglong2*>(&stageA[sl5][c0]);
            ulonglong2 tb = *reinterpret_cast<const ulonglong2*>(&stageB[sl5][c0]);
            if (g5 >= HH) { ta.x = 0; ta.y = 0; tb.x = 0; tb.y = 0; }
            st5a[0] = ta.x; st5a[1] = ta.y; st5b[0] = tb.x; st5b[1] = tb.y;
            {
                int rc = (g5 + 2 < HH) ? (g5 + 2) : (HH - 1);
                cp16(sA[sl5], pa0 + (size_t)rc * WW);
                cp16(sB[sl5], pb0 + (size_t)rc * WW);
                CP_COMMIT();
            }

            CP_WAIT1();  // row g6 complete
            ta = *reinterpret_cast<const ulonglong2*>(&stageA[sl6][c0]);
            tb = *reinterpret_cast<const ulonglong2*>(&stageB[sl6][c0]);
            if (g6 >= HH) { ta.x = 0; ta.y = 0; tb.x = 0; tb.y = 0; }
            st6a[0] = ta.x; st6a[1] = ta.y; st6b[0] = tb.x; st6b[1] = tb.y;
            {
                int rc = (g6 + 2 < HH) ? (g6 + 2) : (HH - 1);
                cp16(sA[sl6], pa0 + (size_t)rc * WW);
                cp16(sB[sl6], pb0 + (size_t)rc * WW);
                CP_COMMIT();
            }
        }

        // ---- vertical conv streamed over 12 source rows ----
        // A = output row i   (taps s=0..10, weight KW[s])
        // B = output row i+1 (taps s=1..11, weight KW[s-1])
        // fields: 0=mu1, 1=mu2, 2=q(a^2+b^2), 3=p(ab)
        u64 A[4][2], B[4][2];
#pragma unroll
        for (int s = 0; s < 12; ++s) {
#pragma unroll
            for (int q = 0; q < 2; ++q) {
                u64 a, b;
                if (s < 10)      { a = rga[s][q]; b = rgb[s][q]; }
                else if (s == 10){ a = st5a[q];   b = st5b[q]; }
                else             { a = st6a[q];   b = st6b[q]; }
                u64 qrow = f2fma(b, b, f2mul(a, a));
                u64 ab = f2mul(a, b);
                if (s <= 10) {
                    const int wi = (s <= 5) ? s : (10 - s);
                    if (s == 0) {
                        A[0][q] = f2mul(WKP[wi], a);
                        A[1][q] = f2mul(WKP[wi], b);
                        A[2][q] = f2mul(WKP[wi], qrow);
                        A[3][q] = f2mul(WKP[wi], ab);
                    } else {
                        A[0][q] = f2fma(WKP[wi], a, A[0][q]);
                        A[1][q] = f2fma(WKP[wi], b, A[1][q]);
                        A[2][q] = f2fma(WKP[wi], qrow, A[2][q]);
                        A[3][q] = f2fma(WKP[wi], ab, A[3][q]);
                    }
                }
                if (s >= 1) {
                    const int k1 = s - 1;
                    const int wi = (k1 <= 5) ? k1 : (10 - k1);
                    if (s == 1) {
                        B[0][q] = f2mul(WKP[wi], a);
                        B[1][q] = f2mul(WKP[wi], b);
                        B[2][q] = f2mul(WKP[wi], qrow);
                        B[3][q] = f2mul(WKP[wi], ab);
                    } else {
                        B[0][q] = f2fma(WKP[wi], a, B[0][q]);
                        B[1][q] = f2fma(WKP[wi], b, B[1][q]);
                        B[2][q] = f2fma(WKP[wi], qrow, B[2][q]);
                        B[3][q] = f2fma(WKP[wi], ab, B[3][q]);
                    }
                }
            }
        }

        // publish vertical sums (one STS.128 per field per row)
#pragma unroll
        for (int f = 0; f < 4; ++f) {
            *reinterpret_cast<ulonglong2*>(&vsbuf[bufA][f][8 + c0]) =
                make_ulonglong2(A[f][0], A[f][1]);
            *reinterpret_cast<ulonglong2*>(&vsbuf[bufB][f][8 + c0]) =
                make_ulonglong2(B[f][0], B[f][1]);
        }

        // advance ring by 2 rows; staged rows enter the ring
#pragma unroll
        for (int k = 0; k < 8; ++k) {
#pragma unroll
            for (int q = 0; q < 2; ++q) {
                rga[k][q] = rga[k + 2][q];
                rgb[k][q] = rgb[k + 2][q];
            }
        }
#pragma unroll
        for (int q = 0; q < 2; ++q) {
            rga[8][q] = st5a[q]; rgb[8][q] = st5b[q];
            rga[9][q] = st6a[q]; rgb[9][q] = st6b[q];
        }

        __syncthreads();  // the only barrier per 2 rows

        // ---- horizontal conv + map, rows A and B (scalar FFMA-imm) ----
#pragma unroll
        for (int r = 0; r < 2; ++r) {
            const int buf = bufA + r;
            float cv[4][4];
#pragma unroll
            for (int f = 0; f < 4; ++f) {
                float v[20];
#pragma unroll
                for (int q5 = 0; q5 < 5; ++q5) {
                    float4 t = *reinterpret_cast<const float4*>(
                        &vsbuf[buf][f][c0 + 4 * q5]);
                    v[4 * q5 + 0] = t.x; v[4 * q5 + 1] = t.y;
                    v[4 * q5 + 2] = t.z; v[4 * q5 + 3] = t.w;
                }
#pragma unroll
                for (int j = 0; j < 4; ++j) {
                    float s = KW[5] * v[8 + j];
#pragma unroll
                    for (int k = 0; k < 11; ++k) {
                        if (k == 5) continue;
                        s += KW[k] * v[3 + j + k];
                    }
                    cv[f][j] = s;
                }
            }
            // scalar SSIM map (literal constants -> no constant registers)
#pragma unroll
            for (int j = 0; j < 4; ++j) {
                float m1 = cv[0][j], m2 = cv[1][j];
                float qv = cv[2][j], pv = cv[3][j];
                float m12 = m1 * m2;
                float sms = fmaf(m1, m1, m2 * m2);
                float num1 = fmaf(m12, 2.f, 1e-4f);
                float num2 = fmaf(pv - m12, 2.f, 9e-4f);
                float den1 = sms + 1e-4f;
                float den2 = (qv - sms) + 9e-4f;
                acc += __fdividef(num1 * num2, den1 * den2);
            }
        }
        // no trailing barrier: next pair writes the other buffer set; reuse
        // of this set is fenced by the next __syncthreads.
    }

    // block reduction -> per-block partial
#pragma unroll
    for (int o = 16; o > 0; o >>= 1)
        acc += __shfl_down_sync(FULLM, acc, o);

    __shared__ float wsum[4];
    __shared__ int is_last;
    if ((tid & 31) == 0) wsum[tid >> 5] = acc;
    __syncthreads();
    if (tid == 0) {
        double s = (double)wsum[0] + (double)wsum[1] + (double)wsum[2] +
                   (double)wsum[3];
        g_partial[blockIdx.y * GX + blockIdx.x] = s;
        __threadfence();
        unsigned old = atomicInc(&g_count, NBLOCKS - 1);  // wraps to 0
        is_last = (old == NBLOCKS - 1);
    }
    __syncthreads();

    // last block finalizes (replay-deterministic: counter wraps to 0)
    if (is_last) {
        __threadfence();
        double s = 0.0;
        for (int i2 = tid; i2 < NBLOCKS; i2 += NTHREADS)
            s += __ldcg(&g_partial[i2]);
#pragma unroll
        for (int o = 16; o > 0; o >>= 1)
            s += __shfl_down_sync(FULLM, s, o);
        __shared__ double dsm[4];
        if ((tid & 31) == 0) dsm[tid >> 5] = s;
        __syncthreads();
        if (tid == 0) {
            double tot = dsm[0] + dsm[1] + dsm[2] + dsm[3];
            out[0] = (float)(1.0 - tot / NPIX);
        }
    }
}

extern "C" void kernel_launch(void* const* d_in, const int* in_sizes, int n_in,
                              void* d_out, int out_size) {
    const float* sr = (const float*)d_in[0];
    const float* hr = (const float*)d_in[1];
    float* out = (float*)d_out;

    dim3 grid(GX, GY);
    ssim_kernel<<<grid, NTHREADS>>>(sr, hr, out);
}